// round 12
// baseline (speedup 1.0000x reference)
#include <cuda_runtime.h>
#include <cuda_bf16.h>

// Problem constants
#define Bn   8
#define Sn   1024
#define Dn   512
#define Hn   8
#define DHn  64
#define BHn  (Bn * Hn)      // 64
#define Mn   (Bn * Sn)      // 8192
#define SCALE 0.044194173824159216f   // 1/sqrt(512)

#define KC    16     // real-k per smem stage (GEMM kernels)
#define AS    20     // A smem stride (u32): conflict-free frags
#define NS128 136    // B smem stride, BN=128: mod 32 == 8 -> conflict-free
#define QS    68     // fused: Q/P smem stride (mod 32 == 4 -> conflict-free A frags)
#define KTS   72     // fused: K smem stride (mod 32 == 8 -> conflict-free B frags)
#define VTS   68     // fused: V^T smem stride (mod 32 == 4 -> conflict-free B frags)

// Scratch (device globals — no allocation allowed). ~357 MB total.
// All activation tensors stored PRE-PACKED as (bf16 hi | bf16 lo<<16) u32.
static __device__ unsigned g_qu[Mn * Dn];   // pack(SCALE*(q + bq + u_bias))
static __device__ unsigned g_qv[Mn * Dn];   // pack(SCALE*(q + bq + v_bias))
static __device__ unsigned g_k[Mn * Dn];
static __device__ unsigned g_v[Mn * Dn];
static __device__ unsigned g_p[Mn * Dn];
static __device__ unsigned g_ctx[Mn * Dn];
static __device__ float    g_sc[(size_t)BHn * Sn * Sn];  // pre-scaled shifted pos
// Packed weights
static __device__ unsigned g_wq[Dn * Dn];
static __device__ unsigned g_wk[Dn * Dn];
static __device__ unsigned g_wv[Dn * Dn];
static __device__ unsigned g_wp[Dn * Dn];
static __device__ unsigned g_wo[Dn * Dn];

// ---------------------------------------------------------------------------
__device__ __forceinline__ unsigned pack_split(float x) {
    __nv_bfloat16 h = __float2bfloat16(x);
    float hf = __bfloat162float(h);
    __nv_bfloat16 l = __float2bfloat16(x - hf);
    return (unsigned)__bfloat16_as_ushort(h) |
           ((unsigned)__bfloat16_as_ushort(l) << 16);
}

__device__ __forceinline__ unsigned swap16(unsigned u) { return (u >> 16) | (u << 16); }

__device__ __forceinline__ void mma_bf16(float c[4], const unsigned a[4],
                                         unsigned b0, unsigned b1) {
    asm volatile(
        "mma.sync.aligned.m16n8k16.row.col.f32.bf16.bf16.f32 "
        "{%0,%1,%2,%3},{%4,%5,%6,%7},{%8,%9},{%0,%1,%2,%3};"
        : "+f"(c[0]), "+f"(c[1]), "+f"(c[2]), "+f"(c[3])
        : "r"(a[0]), "r"(a[1]), "r"(a[2]), "r"(a[3]), "r"(b0), "r"(b1));
}

__device__ __forceinline__ void load8f(float v[8], const float* __restrict__ p) {
    float4 a = *reinterpret_cast<const float4*>(p);
    float4 b = *reinterpret_cast<const float4*>(p + 4);
    v[0] = a.x; v[1] = a.y; v[2] = a.z; v[3] = a.w;
    v[4] = b.x; v[5] = b.y; v[6] = b.z; v[7] = b.w;
}

__device__ __forceinline__ void load8u(unsigned v[8], const unsigned* __restrict__ p) {
    uint4 a = *reinterpret_cast<const uint4*>(p);
    uint4 b = *reinterpret_cast<const uint4*>(p + 4);
    v[0] = a.x; v[1] = a.y; v[2] = a.z; v[3] = a.w;
    v[4] = b.x; v[5] = b.y; v[6] = b.z; v[7] = b.w;
}

// ---------------------------------------------------------------------------
// Pack ALL weights in one launch. grid = (Dn*Dn/256, 5).
// ---------------------------------------------------------------------------
__global__ void pack_all(const float* __restrict__ Wq, const float* __restrict__ Wk,
                         const float* __restrict__ Wv, const float* __restrict__ Wp,
                         const float* __restrict__ Wo) {
    const int sel = blockIdx.y;
    const float* src = (sel == 0) ? Wq : (sel == 1) ? Wk : (sel == 2) ? Wv
                     : (sel == 3) ? Wp : Wo;
    unsigned* dst = (sel == 0) ? g_wq : (sel == 1) ? g_wk : (sel == 2) ? g_wv
                  : (sel == 3) ? g_wp : g_wo;
    const int i = blockIdx.x * 256 + threadIdx.x;
    dst[i] = pack_split(src[i]);
}

// ---------------------------------------------------------------------------
// Warp compute on one KC=16 stage. Warp tile 64 x (NT*8).
// ---------------------------------------------------------------------------
template <int NT, int NS>
__device__ __forceinline__ void warp_mma_stage(const unsigned* __restrict__ A,
                                               const unsigned* __restrict__ B,
                                               int wm, int wn, int lane,
                                               float acc[4][NT][4]) {
    const int g = lane >> 2, kq = lane & 3;
    #pragma unroll
    for (int h = 0; h < 2; h++) {
        unsigned af[4][4];
        #pragma unroll
        for (int t = 0; t < 4; t++) {
            const unsigned* p = A + (wm + t * 16 + g) * AS + h * 8 + kq;
            af[t][0] = p[0]; af[t][1] = p[8 * AS];
            af[t][2] = p[4]; af[t][3] = p[8 * AS + 4];
        }
        #pragma unroll
        for (int u = 0; u < NT; u++) {
            const unsigned* q = B + (h * 8 + kq) * NS + wn + u * 8 + g;
            unsigned b0 = q[0], b1 = q[4 * NS];
            unsigned s0 = swap16(b0), s1 = swap16(b1);
            #pragma unroll
            for (int t = 0; t < 4; t++) {
                mma_bf16(acc[t][u], af[t], b0, b1);   // hi*hi + lo*lo
                mma_bf16(acc[t][u], af[t], s0, s1);   // hi*lo + lo*hi
            }
        }
    }
}

// ---------------------------------------------------------------------------
// Batched projection GEMM: grid (4, 64, 4); blockIdx.z selects the projection.
//   z=0: Q -> g_qu (SCALE*(.+bq+u)) and g_qv (SCALE*(.+bq+v))
//   z=1: K -> g_k; z=2: V -> g_v; z=3: P -> g_p (no bias)
// ---------------------------------------------------------------------------
__global__ __launch_bounds__(256, 2) void proj_gemm(
    const float* __restrict__ Xq, const float* __restrict__ Xk,
    const float* __restrict__ Xv, const float* __restrict__ Xp,
    const float* __restrict__ bq, const float* __restrict__ bk,
    const float* __restrict__ bv,
    const float* __restrict__ ub, const float* __restrict__ vb) {
    const int sel = blockIdx.z;
    const float* X = (sel == 0) ? Xq : (sel == 1) ? Xk : (sel == 2) ? Xv : Xp;
    const unsigned* Wpk = (sel == 0) ? g_wq : (sel == 1) ? g_wk : (sel == 2) ? g_wv : g_wp;
    const float* bias = (sel == 0) ? bq : (sel == 1) ? bk : (sel == 2) ? bv : nullptr;

    __shared__ unsigned Asm[2][128 * AS];
    __shared__ unsigned Bsm[2][KC * NS128];
    const int tid = threadIdx.x, lane = tid & 31, w = tid >> 5;
    const int wm = (w >> 2) * 64, wn = (w & 3) * 32;
    const int mb = blockIdx.y * 128, nb = blockIdx.x * 128;
    const int ar = tid >> 1, akc = (tid & 1) * 8;
    const int br = tid >> 4, bc = (tid & 15) * 8;
    const float* Ag = X + (size_t)(mb + ar) * Dn + akc;
    const unsigned* Bg = Wpk + (size_t)br * Dn + nb + bc;
    float av[8]; unsigned bv8[8];
    load8f(av, Ag); load8u(bv8, Bg);
    float acc[4][4][4] = {};
    int buf = 0;
    for (int k0 = 0; k0 < Dn; k0 += KC) {
        #pragma unroll
        for (int q = 0; q < 8; q++) {
            Asm[buf][ar * AS + akc + q] = pack_split(av[q]);
            Bsm[buf][br * NS128 + bc + q] = bv8[q];
        }
        __syncthreads();
        if (k0 + KC < Dn) {
            load8f(av, Ag + k0 + KC);
            load8u(bv8, Bg + (size_t)(k0 + KC) * Dn);
        }
        warp_mma_stage<4, NS128>(Asm[buf], Bsm[buf], wm, wn, lane, acc);
        buf ^= 1;
    }
    const int g = lane >> 2, kq = lane & 3;
    #pragma unroll
    for (int t = 0; t < 4; t++) {
        #pragma unroll
        for (int u = 0; u < 4; u++) {
            #pragma unroll
            for (int e = 0; e < 4; e++) {
                const int row = mb + wm + t * 16 + g + (e >= 2 ? 8 : 0);
                const int col = nb + wn + u * 8 + 2 * kq + (e & 1);
                const size_t idx = (size_t)row * Dn + col;
                float r = acc[t][u][e];
                if (bias) r += bias[col];
                if (sel == 0) {
                    g_qu[idx] = pack_split(SCALE * (r + ub[col]));
                    g_qv[idx] = pack_split(SCALE * (r + vb[col]));
                } else if (sel == 1) g_k[idx] = pack_split(r);
                else if (sel == 2)   g_v[idx] = pack_split(r);
                else                 g_p[idx] = pack_split(r);
            }
        }
    }
}

// ---------------------------------------------------------------------------
// Output GEMM: out = unpack(g_ctx) @ Wo + bo. Both operands pre-packed.
// ---------------------------------------------------------------------------
__global__ __launch_bounds__(256, 2) void out_gemm(const float* __restrict__ bias,
                                                   float* __restrict__ C) {
    __shared__ unsigned Asm[2][128 * AS];
    __shared__ unsigned Bsm[2][KC * NS128];
    const int tid = threadIdx.x, lane = tid & 31, w = tid >> 5;
    const int wm = (w >> 2) * 64, wn = (w & 3) * 32;
    const int mb = blockIdx.y * 128, nb = blockIdx.x * 128;
    const int ar = tid >> 1, akc = (tid & 1) * 8;
    const int br = tid >> 4, bc = (tid & 15) * 8;
    const unsigned* Ag = g_ctx + (size_t)(mb + ar) * Dn + akc;
    const unsigned* Bg = g_wo + (size_t)br * Dn + nb + bc;
    unsigned av[8], bv[8];
    load8u(av, Ag); load8u(bv, Bg);
    float acc[4][4][4] = {};
    int buf = 0;
    for (int k0 = 0; k0 < Dn; k0 += KC) {
        #pragma unroll
        for (int q = 0; q < 8; q++) {
            Asm[buf][ar * AS + akc + q] = av[q];
            Bsm[buf][br * NS128 + bc + q] = bv[q];
        }
        __syncthreads();
        if (k0 + KC < Dn) {
            load8u(av, Ag + k0 + KC);
            load8u(bv, Bg + (size_t)(k0 + KC) * Dn);
        }
        warp_mma_stage<4, NS128>(Asm[buf], Bsm[buf], wm, wn, lane, acc);
        buf ^= 1;
    }
    const int g = lane >> 2, kq = lane & 3;
    #pragma unroll
    for (int t = 0; t < 4; t++) {
        #pragma unroll
        for (int u = 0; u < 4; u++) {
            const int row = mb + wm + t * 16 + g;
            const int col = nb + wn + u * 8 + 2 * kq;
            const float b0 = bias[col], b1 = bias[col + 1];
            float2 lo; lo.x = acc[t][u][0] + b0; lo.y = acc[t][u][1] + b1;
            float2 hi; hi.x = acc[t][u][2] + b0; hi.y = acc[t][u][3] + b1;
            *reinterpret_cast<float2*>(C + (size_t)row * Dn + col) = lo;
            *reinterpret_cast<float2*>(C + (size_t)(row + 8) * Dn + col) = hi;
        }
    }
}

// ---------------------------------------------------------------------------
// Score pass 0, per (b,h): P[i,c]=SCALE*(q_i+vb).p_c scattered SHIFTED:
//   c >= S-1-i -> R[i, c-S+1+i];  c < S-1-i -> R[i-1, c+i+1] (dropped at i==0)
// R[i,i+1] never written (identically 0; masked at read time in attn_fused).
// ---------------------------------------------------------------------------
__global__ __launch_bounds__(256, 2) void score_pos() {
    const int bh = blockIdx.z;
    const int b = bh >> 3, h = bh & 7;
    const int ib = blockIdx.y * 128, jb = blockIdx.x * 128;
    const unsigned* Ag = g_qv + (size_t)(b * Sn + ib) * Dn + h * DHn;
    const unsigned* Bg = g_p + (size_t)(b * Sn + jb) * Dn + h * DHn;
    __shared__ unsigned Asm[2][128 * AS];
    __shared__ unsigned Bsm[2][KC * NS128];
    const int tid = threadIdx.x, lane = tid & 31, w = tid >> 5;
    const int wm = (w >> 2) * 64, wn = (w & 3) * 32;
    const int ar = tid >> 1, akc = (tid & 1) * 8;
    const unsigned* Agr = Ag + (size_t)ar * Dn + akc;
    const unsigned* Bgr = Bg + (size_t)ar * Dn + akc;   // transposed source
    unsigned av[8], bv[8];
    load8u(av, Agr); load8u(bv, Bgr);
    float acc[4][4][4] = {};
    int buf = 0;
    #pragma unroll
    for (int k0 = 0; k0 < DHn; k0 += KC) {
        #pragma unroll
        for (int q = 0; q < 8; q++) {
            Asm[buf][ar * AS + akc + q] = av[q];
            Bsm[buf][(akc + q) * NS128 + ar] = bv[q];
        }
        __syncthreads();
        if (k0 + KC < DHn) {
            load8u(av, Agr + k0 + KC);
            load8u(bv, Bgr + k0 + KC);
        }
        warp_mma_stage<4, NS128>(Asm[buf], Bsm[buf], wm, wn, lane, acc);
        buf ^= 1;
    }
    const size_t base = (size_t)bh * Sn * Sn;
    const int g = lane >> 2, kq = lane & 3;
    #pragma unroll
    for (int t = 0; t < 4; t++) {
        #pragma unroll
        for (int u = 0; u < 4; u++) {
            #pragma unroll
            for (int e = 0; e < 4; e++) {
                const int i = ib + wm + t * 16 + g + (e >= 2 ? 8 : 0);
                const int j = jb + wn + u * 8 + 2 * kq + (e & 1);
                const float val = acc[t][u][e];
                if (j >= Sn - 1 - i)
                    g_sc[base + (size_t)i * Sn + (j - Sn + 1 + i)] = val;
                else if (i > 0)
                    g_sc[base + (size_t)(i - 1) * Sn + (j + i + 1)] = val;
            }
        }
    }
}

// ---------------------------------------------------------------------------
// Fused flash attention, FA-2 warp layout: warp w owns rows [16w, 16w+16)
// and the FULL 64-col j tile. Softmax stats are warp-local (shfl over kq
// lanes only). P is warp-private smem. 2 __syncthreads per j-tile (K/V stage).
// K staged [k][j] stride 72; V staged transposed [d][j] stride 68.
// ---------------------------------------------------------------------------
#define Q_U32   (128 * QS)       // 8704
#define KT_U32  (64 * KTS)       // 4608
#define VT_U32  (64 * VTS)       // 4352
#define P_U32   (128 * QS)       // 8704
#define FUSED_SMEM_BYTES ((Q_U32 + KT_U32 + VT_U32 + P_U32) * 4)   // ~103 KB

__global__ __launch_bounds__(256, 2) void attn_fused() {
    extern __shared__ unsigned sm[];
    unsigned* Qsm = sm;                              // 128 x QS
    unsigned* Ksm = sm + Q_U32;                      // 64 x KTS  [k][j]
    unsigned* Vsm = sm + Q_U32 + KT_U32;             // 64 x VTS  [d][j]
    unsigned* Psm = sm + Q_U32 + KT_U32 + VT_U32;    // 128 x QS

    const int bh = blockIdx.y;
    const int b = bh >> 3, h = bh & 7;
    const int ib = blockIdx.x * 128;
    const int tid = threadIdx.x, lane = tid & 31, w = tid >> 5;
    const int g = lane >> 2, kq = lane & 3;
    const int r0 = w * 16 + g;           // this lane's first local row
    const size_t scbase = (size_t)bh * Sn * Sn;

    // Load Q strip (pre-packed, pre-scaled, u_bias folded).
    {
        const int r = tid >> 1, off = (tid & 1) * 32;
        const unsigned* src = g_qu + (size_t)(b * Sn + ib + r) * Dn + h * DHn + off;
        #pragma unroll
        for (int c = 0; c < 32; c += 8) {
            unsigned v[8]; load8u(v, src + c);
            #pragma unroll
            for (int q = 0; q < 8; q++) Qsm[r * QS + off + c + q] = v[q];
        }
    }

    float m0 = -1e30f, m1 = -1e30f, l0 = 0.f, l1 = 0.f;
    float acc_o[8][4] = {};

    const int jld = tid & 63, kld = (tid >> 6) * 16;   // tile loader mapping

    for (int jt = 0; jt < 16; jt++) {
        const int j0 = jt * 64;
        __syncthreads();   // all warps done with prev K/V before overwrite
        // Stage K [k][j] and V^T [d][j] for this tile.
        {
            const size_t rowoff = (size_t)(b * Sn + j0 + jld) * Dn + h * DHn + kld;
            unsigned vk[16], vv[16];
            load8u(vk, g_k + rowoff); load8u(vk + 8, g_k + rowoff + 8);
            load8u(vv, g_v + rowoff); load8u(vv + 8, g_v + rowoff + 8);
            #pragma unroll
            for (int c = 0; c < 16; c++) {
                Ksm[(kld + c) * KTS + jld] = vk[c];
                Vsm[(kld + c) * VTS + jld] = vv[c];
            }
        }
        __syncthreads();

        // Score mma: m16 x n64 x k64 per warp.
        float acc_s[8][4] = {};
        #pragma unroll
        for (int hh = 0; hh < 8; hh++) {
            unsigned af[4];
            const unsigned* p = Qsm + r0 * QS + hh * 8 + kq;
            af[0] = p[0]; af[1] = p[8 * QS]; af[2] = p[4]; af[3] = p[8 * QS + 4];
            #pragma unroll
            for (int u = 0; u < 8; u++) {
                const unsigned* q = Ksm + (hh * 8 + kq) * KTS + u * 8 + g;
                unsigned b0 = q[0], b1 = q[4 * KTS];
                unsigned s0 = swap16(b0), s1 = swap16(b1);
                mma_bf16(acc_s[u], af, b0, b1);
                mma_bf16(acc_s[u], af, s0, s1);
            }
        }

        // Pos bias (pre-scaled; j==i+1 slot forced 0) + running row max.
        const int i0 = ib + r0, i1 = i0 + 8;
        const float* row0 = g_sc + scbase + (size_t)i0 * Sn + j0;
        const float* row1 = g_sc + scbase + (size_t)i1 * Sn + j0;
        float pm0 = -1e30f, pm1 = -1e30f;
        #pragma unroll
        for (int u = 0; u < 8; u++) {
            const int jl = u * 8 + 2 * kq;
            const int jg = j0 + jl;
            float2 pv0 = *reinterpret_cast<const float2*>(row0 + jl);
            float2 pv1 = *reinterpret_cast<const float2*>(row1 + jl);
            float s00 = acc_s[u][0] + ((jg     == i0 + 1) ? 0.f : pv0.x);
            float s01 = acc_s[u][1] + ((jg + 1 == i0 + 1) ? 0.f : pv0.y);
            float s10 = acc_s[u][2] + ((jg     == i1 + 1) ? 0.f : pv1.x);
            float s11 = acc_s[u][3] + ((jg + 1 == i1 + 1) ? 0.f : pv1.y);
            acc_s[u][0] = s00; acc_s[u][1] = s01; acc_s[u][2] = s10; acc_s[u][3] = s11;
            pm0 = fmaxf(pm0, fmaxf(s00, s01));
            pm1 = fmaxf(pm1, fmaxf(s10, s11));
        }
        pm0 = fmaxf(pm0, __shfl_xor_sync(0xffffffffu, pm0, 1));
        pm0 = fmaxf(pm0, __shfl_xor_sync(0xffffffffu, pm0, 2));
        pm1 = fmaxf(pm1, __shfl_xor_sync(0xffffffffu, pm1, 1));
        pm1 = fmaxf(pm1, __shfl_xor_sync(0xffffffffu, pm1, 2));
        const float mn0 = fmaxf(m0, pm0), mn1 = fmaxf(m1, pm1);
        const float al0 = __expf(m0 - mn0), al1 = __expf(m1 - mn1);
        m0 = mn0; m1 = mn1; l0 *= al0; l1 *= al1;
        #pragma unroll
        for (int u = 0; u < 8; u++) {
            acc_o[u][0] *= al0; acc_o[u][1] *= al0;
            acc_o[u][2] *= al1; acc_o[u][3] *= al1;
        }

        // P = exp(s - m) -> warp-private Psm (packed split).
        #pragma unroll
        for (int u = 0; u < 8; u++) {
            const int jl = u * 8 + 2 * kq;
            float p00 = __expf(acc_s[u][0] - m0);
            float p01 = __expf(acc_s[u][1] - m0);
            float p10 = __expf(acc_s[u][2] - m1);
            float p11 = __expf(acc_s[u][3] - m1);
            l0 += p00 + p01; l1 += p10 + p11;
            uint2 w0; w0.x = pack_split(p00); w0.y = pack_split(p01);
            uint2 w1; w1.x = pack_split(p10); w1.y = pack_split(p11);
            *reinterpret_cast<uint2*>(Psm + r0 * QS + jl) = w0;
            *reinterpret_cast<uint2*>(Psm + (r0 + 8) * QS + jl) = w1;
        }
        __syncwarp();

        // AV mma: m16 x n64(d) x k64(j), all warp-local.
        #pragma unroll
        for (int hh = 0; hh < 8; hh++) {
            unsigned af[4];
            const unsigned* p = Psm + r0 * QS + hh * 8 + kq;
            af[0] = p[0]; af[1] = p[8 * QS]; af[2] = p[4]; af[3] = p[8 * QS + 4];
            #pragma unroll
            for (int u = 0; u < 8; u++) {
                const unsigned* q = Vsm + (u * 8 + g) * VTS + hh * 8 + kq;
                unsigned b0 = q[0], b1 = q[4];
                unsigned s0 = swap16(b0), s1 = swap16(b1);
                mma_bf16(acc_o[u], af, b0, b1);
                mma_bf16(acc_o[u], af, s0, s1);
            }
        }
    }

    // Final row sums (kq lanes) and normalized packed output.
    l0 += __shfl_xor_sync(0xffffffffu, l0, 1);
    l0 += __shfl_xor_sync(0xffffffffu, l0, 2);
    l1 += __shfl_xor_sync(0xffffffffu, l1, 1);
    l1 += __shfl_xor_sync(0xffffffffu, l1, 2);
    const float inv0 = 1.0f / l0, inv1 = 1.0f / l1;
    #pragma unroll
    for (int u = 0; u < 8; u++) {
        #pragma unroll
        for (int e = 0; e < 4; e++) {
            const int i = ib + r0 + (e >= 2 ? 8 : 0);
            const int col = h * DHn + u * 8 + 2 * kq + (e & 1);
            g_ctx[(size_t)(b * Sn + i) * Dn + col] =
                pack_split(acc_o[u][e] * (e >= 2 ? inv1 : inv0));
        }
    }
}

// ---------------------------------------------------------------------------
extern "C" void kernel_launch(void* const* d_in, const int* in_sizes, int n_in,
                              void* d_out, int out_size) {
    (void)in_sizes; (void)n_in; (void)out_size;
    const float* query = (const float*)d_in[0];
    const float* key   = (const float*)d_in[1];
    const float* value = (const float*)d_in[2];
    const float* pemb  = (const float*)d_in[3];
    const float* Wq    = (const float*)d_in[4];
    const float* bq    = (const float*)d_in[5];
    const float* Wk    = (const float*)d_in[6];
    const float* bk    = (const float*)d_in[7];
    const float* Wv    = (const float*)d_in[8];
    const float* bv    = (const float*)d_in[9];
    const float* Wp    = (const float*)d_in[10];
    const float* u_bias = (const float*)d_in[11];
    const float* v_bias = (const float*)d_in[12];
    const float* Wo    = (const float*)d_in[13];
    const float* bo    = (const float*)d_in[14];
    float* out = (float*)d_out;

    cudaFuncSetAttribute(attn_fused, cudaFuncAttributeMaxDynamicSharedMemorySize,
                         FUSED_SMEM_BYTES);

    dim3 gpack(Dn * Dn / 256, 5);
    pack_all<<<gpack, 256>>>(Wq, Wk, Wv, Wp, Wo);

    dim3 gproj(Dn / 128, Mn / 128, 4);    // (4, 64, 4) — all projections, one launch
    proj_gemm<<<gproj, 256>>>(query, key, value, pemb, bq, bk, bv, u_bias, v_bias);

    dim3 gsc(Sn / 128, Sn / 128, BHn);    // (8, 8, 64)
    score_pos<<<gsc, 256>>>();            // pre-scaled pos, scattered -> g_sc

    dim3 gf(Sn / 128, BHn);               // (8, 64)
    attn_fused<<<gf, 256, FUSED_SMEM_BYTES>>>();

    out_gemm<<<dim3(Dn / 128, Mn / 128), 256>>>(bo, out);
}